// round 14
// baseline (speedup 1.0000x reference)
#include <cuda_runtime.h>
#include <cuda_bf16.h>
#include <cuda_fp16.h>
#include <math_constants.h>
#include <cstdint>

// Problem constants
#define NTOK 2048
#define BSZ  2
#define EMB  1024
#define NH   16
#define HD   64
#define MROWS (NTOK*BSZ)      // 4096
#define F3   (3*EMB)          // 3072
#define QSCALE 0.1803368801111204f   // 0.125 * log2(e)

// -------------------- device scratch (allocation-free) ----------------------
__device__ __half g_sh[(size_t)MROWS * EMB];   // seq fp16 (1-pass)
__device__ __half g_wq[(size_t)F3 * EMB];      // w_qkv fp16 (1-pass)
__device__ __half g_wo[(size_t)EMB * EMB];     // w_out fp16 (1-pass)
__device__ __half g_qf[(size_t)MROWS * EMB];   // Q fp16 (pre-scaled)
__device__ __half g_kf[(size_t)MROWS * EMB];   // K fp16
__device__ __half g_vh0[(size_t)MROWS * EMB];  // V fp16 (token-major)
__device__ __half g_ch[(size_t)MROWS * EMB];   // attn out fp16 (1-pass)

// -------------------- PTX helpers -------------------------------------------
__device__ __forceinline__ uint32_t s2u(const void* p) {
    uint32_t a;
    asm("{ .reg .u64 t; cvta.to.shared.u64 t, %1; cvt.u32.u64 %0, t; }"
        : "=r"(a) : "l"(p));
    return a;
}

__device__ __forceinline__ void cp16(uint32_t dst, const void* src) {
    asm volatile("cp.async.cg.shared.global [%0], [%1], 16;"
                 :: "r"(dst), "l"(src) : "memory");
}
#define CP_COMMIT() asm volatile("cp.async.commit_group;" ::: "memory")

__device__ __forceinline__ void ldsm4(uint32_t* r, uint32_t a) {
    asm volatile("ldmatrix.sync.aligned.m8n8.x4.shared.b16 {%0,%1,%2,%3}, [%4];"
                 : "=r"(r[0]), "=r"(r[1]), "=r"(r[2]), "=r"(r[3]) : "r"(a));
}

// transposing variant (V: token-major smem -> B fragments)
__device__ __forceinline__ void ldsm4t(uint32_t* r, uint32_t a) {
    asm volatile("ldmatrix.sync.aligned.m8n8.x4.trans.shared.b16 {%0,%1,%2,%3}, [%4];"
                 : "=r"(r[0]), "=r"(r[1]), "=r"(r[2]), "=r"(r[3]) : "r"(a));
}

// fp32-accumulate HMMA
__device__ __forceinline__ void mma16816h(float* c, const uint32_t* a,
                                           const uint32_t* b) {
    asm volatile(
        "mma.sync.aligned.m16n8k16.row.col.f32.f16.f16.f32 "
        "{%0,%1,%2,%3}, {%4,%5,%6,%7}, {%8,%9}, {%0,%1,%2,%3};"
        : "+f"(c[0]), "+f"(c[1]), "+f"(c[2]), "+f"(c[3])
        : "r"(a[0]), "r"(a[1]), "r"(a[2]), "r"(a[3]), "r"(b[0]), "r"(b[1]));
}

// fp16-accumulate HMMA (QK logits)
__device__ __forceinline__ void mma16816hh(uint32_t* c, const uint32_t* a,
                                            const uint32_t* b) {
    asm volatile(
        "mma.sync.aligned.m16n8k16.row.col.f16.f16.f16.f16 "
        "{%0,%1}, {%2,%3,%4,%5}, {%6,%7}, {%0,%1};"
        : "+r"(c[0]), "+r"(c[1])
        : "r"(a[0]), "r"(a[1]), "r"(a[2]), "r"(a[3]), "r"(b[0]), "r"(b[1]));
}

__device__ __forceinline__ float ex2(float x) {
    float y;
    asm("ex2.approx.f32 %0, %1;" : "=f"(y) : "f"(x));
    return y;
}

__device__ __forceinline__ uint32_t hmax2u(uint32_t a, uint32_t b) {
    uint32_t d;
    asm("max.f16x2 %0, %1, %2;" : "=r"(d) : "r"(a), "r"(b));
    return d;
}

__device__ __forceinline__ uint32_t hsub2u(uint32_t a, uint32_t b) {
    uint32_t d;
    asm("sub.f16x2 %0, %1, %2;" : "=r"(d) : "r"(a), "r"(b));
    return d;
}

__device__ __forceinline__ uint32_t ex2h2(uint32_t a) {
    uint32_t d;
    asm("ex2.approx.f16x2 %0, %1;" : "=r"(d) : "r"(a));
    return d;
}

__device__ __forceinline__ uint32_t pack2h(float a, float b) {
    __half2 t = __floats2half2_rn(a, b);
    return *reinterpret_cast<uint32_t*>(&t);
}

__device__ __forceinline__ float2 unpack2h(uint32_t u) {
    __half2 t = *reinterpret_cast<__half2*>(&u);
    return __half22float2(t);
}

// -------------------- fused convert: 3 arrays fp32 -> fp16 ------------------
#define N4_SEQ (MROWS * EMB / 4)
#define N4_WQ  (F3 * EMB / 4)
#define N4_WO  (EMB * EMB / 4)

__global__ void convert_all_kernel(const float4* __restrict__ seq,
                                   const float4* __restrict__ wq,
                                   const float4* __restrict__ wo) {
    int i = blockIdx.x * blockDim.x + threadIdx.x;
    const float4* src;
    uint2* dst;
    int k;
    if (i < N4_SEQ) {
        src = seq; dst = (uint2*)g_sh; k = i;
    } else if (i < N4_SEQ + N4_WQ) {
        src = wq; dst = (uint2*)g_wq; k = i - N4_SEQ;
    } else if (i < N4_SEQ + N4_WQ + N4_WO) {
        src = wo; dst = (uint2*)g_wo; k = i - N4_SEQ - N4_WQ;
    } else return;
    float4 x = src[k];
    uint2 o;
    o.x = pack2h(x.x, x.y);
    o.y = pack2h(x.z, x.w);
    dst[k] = o;
}

// -------------------- fp16 1-pass GEMM, K-chunk 32 ---------------------------
// C = A[M][K] * B[N][K]^T + bias[N]; CTA 128x128, 8 warps (32x64 warp tile).
// qkvmode=0: C fp32.  qkvmode=1: N=3072; comp0->g_qf(xQSCALE), comp1->g_kf,
// comp2->g_vh0 (fp16).
#define PITCH  80
#define TILEB  (128 * PITCH)       // 10240
#define STAGEB (2 * TILEB)         // 20480: A, B
#define GSTG   4
#define GSMEM  (GSTG * STAGEB)     // 81920 -> 2 CTAs/SM

#define ARR_A  0
#define ARR_B  TILEB

__global__ void __launch_bounds__(256, 2) gemm_mma_kernel(
    const __half* __restrict__ A, const __half* __restrict__ B,
    const float* __restrict__ bias, float* __restrict__ C,
    int N, int K, int qkvmode)
{
    extern __shared__ char smem[];
    const uint32_t sb = s2u(smem);
    const int tid  = threadIdx.x;
    const int lane = tid & 31;
    const int warp = tid >> 5;
    const int wm   = warp & 3;
    const int wn   = warp >> 2;
    const int row0 = blockIdx.y * 128;
    const int col0 = blockIdx.x * 128;

    float acc[2][8][4];
    #pragma unroll
    for (int i = 0; i < 2; i++)
        #pragma unroll
        for (int j = 0; j < 8; j++)
            #pragma unroll
            for (int v = 0; v < 4; v++) acc[i][j][v] = 0.f;

    const uint32_t a_off = (uint32_t)(lane & 15) * PITCH + (lane >> 4) * 16;
    const uint32_t b_off = (uint32_t)((lane & 7) + ((lane >> 4) & 1) * 8) * PITCH
                         + ((lane >> 3) & 1) * 16;

    const int pr   = tid >> 1;
    const int pseg = (tid & 1) * 2;
    const int nch  = K / 32;

    #define PRODUCE(c)                                                        \
    do {                                                                      \
        uint32_t base = sb + (uint32_t)((c) & 3) * STAGEB;                    \
        size_t gA = (size_t)(row0 + pr) * K + (c) * 32 + pseg * 8;            \
        size_t gB = (size_t)(col0 + pr) * K + (c) * 32 + pseg * 8;            \
        uint32_t so = (uint32_t)pr * PITCH + pseg * 16;                       \
        cp16(base + ARR_A + so,      A + gA);                                 \
        cp16(base + ARR_A + so + 16, A + gA + 8);                             \
        cp16(base + ARR_B + so,      B + gB);                                 \
        cp16(base + ARR_B + so + 16, B + gB + 8);                             \
    } while (0)

    PRODUCE(0); CP_COMMIT();
    PRODUCE(1); CP_COMMIT();
    PRODUCE(2); CP_COMMIT();

    for (int c = 0; c < nch; c++) {
        asm volatile("cp.async.wait_group 2;" ::: "memory");
        __syncthreads();

        if (c + 3 < nch) PRODUCE(c + 3);
        CP_COMMIT();

        const uint32_t st = sb + (uint32_t)(c & 3) * STAGEB;

        #pragma unroll
        for (int ks = 0; ks < 2; ks++) {
            const uint32_t brow = ARR_B + (uint32_t)(wn * 64) * PITCH
                                + ks * 32 + b_off;
            uint32_t ah[2][4], bfr[2][4];
            ldsm4(bfr[0], st + brow);
            #pragma unroll
            for (int mt = 0; mt < 2; mt++) {
                uint32_t ra = (uint32_t)(wm * 32 + mt * 16) * PITCH
                            + ks * 32 + a_off;
                ldsm4(ah[mt], st + ARR_A + ra);
            }
            #pragma unroll
            for (int nt = 0; nt < 4; nt++) {
                if (nt < 3)
                    ldsm4(bfr[(nt + 1) & 1],
                          st + brow + (uint32_t)((nt + 1) * 16) * PITCH);
                const uint32_t* b4 = bfr[nt & 1];
                mma16816h(acc[0][2 * nt],     ah[0], b4);
                mma16816h(acc[1][2 * nt],     ah[1], b4);
                mma16816h(acc[0][2 * nt + 1], ah[0], b4 + 2);
                mma16816h(acc[1][2 * nt + 1], ah[1], b4 + 2);
            }
        }
    }

    const int tr = lane >> 2;
    const int tc = (lane & 3) * 2;
    const int comp = col0 >> 10;
    #pragma unroll
    for (int mt = 0; mt < 2; mt++) {
        #pragma unroll
        for (int n8 = 0; n8 < 8; n8++) {
            int r  = row0 + wm * 32 + mt * 16 + tr;
            int cc = col0 + wn * 64 + n8 * 8 + tc;
            float b0 = bias[cc], b1 = bias[cc + 1];
            float v0 = acc[mt][n8][0] + b0;
            float v1 = acc[mt][n8][1] + b1;
            float v2 = acc[mt][n8][2] + b0;
            float v3 = acc[mt][n8][3] + b1;
            if (qkvmode) {
                int ccl = cc - (comp << 10);
                size_t o0 = (size_t)r * EMB + ccl;
                size_t o1 = (size_t)(r + 8) * EMB + ccl;
                if (comp == 0) {
                    *(uint32_t*)(g_qf + o0) = pack2h(v0 * QSCALE, v1 * QSCALE);
                    *(uint32_t*)(g_qf + o1) = pack2h(v2 * QSCALE, v3 * QSCALE);
                } else if (comp == 1) {
                    *(uint32_t*)(g_kf + o0) = pack2h(v0, v1);
                    *(uint32_t*)(g_kf + o1) = pack2h(v2, v3);
                } else {
                    *(uint32_t*)(g_vh0 + o0) = pack2h(v0, v1);
                    *(uint32_t*)(g_vh0 + o1) = pack2h(v2, v3);
                }
            } else {
                *(float2*)(C + (size_t)r * N + cc)       = make_float2(v0, v1);
                *(float2*)(C + (size_t)(r + 8) * N + cc) = make_float2(v2, v3);
            }
        }
    }
}

// -------------------- flash attention (128-key stages, 2 halves) ------------
#define AQ    0
#define ABUF  16384
#define ASTG  32768                 // K 16KB (128 rows) + V 16KB
#define A_K   0
#define A_VH  16384
#define ASTAGES 3
#define ATTN_SMEM (ABUF + ASTAGES * ASTG)   // 114688 -> 2 CTAs/SM

#define ASWZ(row, seg) ((uint32_t)(row) * 128 + ((uint32_t)((seg) ^ ((row) & 7)) * 16))

__global__ void __launch_bounds__(256, 2) attn_mma_kernel()
{
    extern __shared__ char smem[];
    const uint32_t sb = s2u(smem);
    const int tid  = threadIdx.x;
    const int lane = tid & 31;
    const int warp = tid >> 5;
    const int qt = blockIdx.x;
    const int bh = blockIdx.y;
    const int b  = bh & 1;
    const int h  = bh >> 1;

    {
        int prow = tid >> 1;
        int psb  = (tid & 1) * 4;
        int qtok = qt * 128 + prow;
        size_t gq = (size_t)(qtok * 2 + b) * EMB + h * HD + psb * 8;
        #pragma unroll
        for (int j = 0; j < 4; j++)
            cp16(sb + AQ + ASWZ(prow, psb + j), g_qf + gq + j * 8);
    }

    const int prow = tid >> 1;          // 0..127
    const int psb  = (tid & 1) * 4;     // seg base 0 or 4

    // stage = 128 keys: K rows 0..127, V rows 0..127 (token-major)
    #define APROD(kt)                                                         \
    do {                                                                      \
        uint32_t bufb = sb + ABUF + (uint32_t)((kt) % ASTAGES) * ASTG;        \
        int tok = (kt) * 128 + prow;                                          \
        size_t g = (size_t)(tok * 2 + b) * EMB + h * HD;                      \
        _Pragma("unroll")                                                     \
        for (int j = 0; j < 4; j++) {                                         \
            int seg = psb + j;                                                \
            uint32_t o = ASWZ(prow, seg);                                     \
            cp16(bufb + A_K  + o, g_kf  + g + seg * 8);                       \
            cp16(bufb + A_VH + o, g_vh0 + g + seg * 8);                       \
        }                                                                     \
    } while (0)

    APROD(0); CP_COMMIT();
    APROD(1); CP_COMMIT();

    float o[8][4];
    #pragma unroll
    for (int j = 0; j < 8; j++)
        #pragma unroll
        for (int v = 0; v < 4; v++) o[j][v] = 0.f;
    float m0 = -CUDART_INF_F, m1 = -CUDART_INF_F, l0 = 0.f, l1 = 0.f;
    uint32_t qf[4][4];

    const int brow_l = (lane & 7) + ((lane >> 4) & 1) * 8;  // K (non-trans)
    const int bseg_l = (lane >> 3) & 1;
    const int trow_l = lane & 15;                            // V (trans)
    const int tseg_l = lane >> 4;

    const int NKT = NTOK / 128;   // 16 stages of 128 keys
    for (int kt = 0; kt < NKT; kt++) {
        asm volatile("cp.async.wait_group 1;" ::: "memory");
        __syncthreads();

        if (kt + 2 < NKT) APROD(kt + 2);
        CP_COMMIT();

        const uint32_t kb = sb + ABUF + (uint32_t)(kt % ASTAGES) * ASTG;

        if (kt == 0) {
            #pragma unroll
            for (int ks = 0; ks < 4; ks++) {
                int row = warp * 16 + (lane & 15);
                int seg = ks * 2 + (lane >> 4);
                ldsm4(qf[ks], sb + AQ + ASWZ(row, seg));
            }
        }

        // two 64-key softmax halves within this 128-key stage
        #pragma unroll
        for (int hf = 0; hf < 2; hf++) {
            const uint32_t kbk = kb + A_K  + (uint32_t)hf * 8192;
            const uint32_t kbv = kb + A_VH + (uint32_t)hf * 8192;

            // S = Q K^T with fp16 accumulators
            uint32_t sh2[8][2];
            #pragma unroll
            for (int j = 0; j < 8; j++) { sh2[j][0] = 0u; sh2[j][1] = 0u; }

            {
                uint32_t kbf[2][4];
                ldsm4(kbf[0], kbk + ASWZ(brow_l, bseg_l));
                #pragma unroll
                for (int it = 0; it < 16; it++) {
                    const int ks = it >> 2, nt = it & 3;
                    if (it < 15) {
                        const int ks2 = (it + 1) >> 2, nt2 = (it + 1) & 3;
                        ldsm4(kbf[(it + 1) & 1],
                              kbk + ASWZ(nt2 * 16 + brow_l, ks2 * 2 + bseg_l));
                    }
                    const uint32_t* k4 = kbf[it & 1];
                    mma16816hh(sh2[2 * nt],     qf[ks], k4);
                    mma16816hh(sh2[2 * nt + 1], qf[ks], k4 + 2);
                }
            }

            // row maxes (packed f16x2 tree + cross-lane)
            uint32_t mx0 = sh2[0][0], mx1 = sh2[0][1];
            #pragma unroll
            for (int j = 1; j < 8; j++) {
                mx0 = hmax2u(mx0, sh2[j][0]);
                mx1 = hmax2u(mx1, sh2[j][1]);
            }
            mx0 = hmax2u(mx0, __shfl_xor_sync(0xffffffffu, mx0, 1));
            mx0 = hmax2u(mx0, __shfl_xor_sync(0xffffffffu, mx0, 2));
            mx1 = hmax2u(mx1, __shfl_xor_sync(0xffffffffu, mx1, 1));
            mx1 = hmax2u(mx1, __shfl_xor_sync(0xffffffffu, mx1, 2));
            float2 f0 = unpack2h(mx0);
            float2 f1 = unpack2h(mx1);
            float cm0 = fmaxf(f0.x, f0.y);
            float cm1 = fmaxf(f1.x, f1.y);

            float nm0 = fmaxf(m0, cm0), nm1 = fmaxf(m1, cm1);
            float al0 = ex2(m0 - nm0),  al1 = ex2(m1 - nm1);
            m0 = nm0; m1 = nm1;

            uint32_t nm0h, nm1h;
            {
                __half2 t0 = __float2half2_rn(nm0);
                __half2 t1 = __float2half2_rn(nm1);
                nm0h = *reinterpret_cast<uint32_t*>(&t0);
                nm1h = *reinterpret_cast<uint32_t*>(&t1);
            }

            // P fragments in packed half2 (a-fragment layout)
            uint32_t pf[4][4];
            #pragma unroll
            for (int ks = 0; ks < 4; ks++) {
                pf[ks][0] = ex2h2(hsub2u(sh2[2 * ks][0],     nm0h));
                pf[ks][1] = ex2h2(hsub2u(sh2[2 * ks][1],     nm1h));
                pf[ks][2] = ex2h2(hsub2u(sh2[2 * ks + 1][0], nm0h));
                pf[ks][3] = ex2h2(hsub2u(sh2[2 * ks + 1][1], nm1h));
            }

            // row sums: unpack to fp32 (exact; FMA pipe)
            float rs0 = 0.f, rs1 = 0.f;
            #pragma unroll
            for (int ks = 0; ks < 4; ks++) {
                float2 a0 = unpack2h(pf[ks][0]);
                float2 a2 = unpack2h(pf[ks][2]);
                rs0 += (a0.x + a0.y) + (a2.x + a2.y);
                float2 a1 = unpack2h(pf[ks][1]);
                float2 a3 = unpack2h(pf[ks][3]);
                rs1 += (a1.x + a1.y) + (a3.x + a3.y);
            }
            rs0 += __shfl_xor_sync(0xffffffffu, rs0, 1);
            rs0 += __shfl_xor_sync(0xffffffffu, rs0, 2);
            rs1 += __shfl_xor_sync(0xffffffffu, rs1, 1);
            rs1 += __shfl_xor_sync(0xffffffffu, rs1, 2);
            l0 = l0 * al0 + rs0;
            l1 = l1 * al1 + rs1;

            #pragma unroll
            for (int j = 0; j < 8; j++) {
                o[j][0] *= al0; o[j][1] *= al0;
                o[j][2] *= al1; o[j][3] *= al1;
            }

            // O += P V  (V token-major, transposed by ldsm.trans)
            {
                uint32_t vhb[2][4];
                ldsm4t(vhb[0], kbv + ASWZ(trow_l, tseg_l));
                #pragma unroll
                for (int it = 0; it < 16; it++) {
                    const int ks = it >> 2, nt = it & 3;
                    if (it < 15) {
                        const int ks2 = (it + 1) >> 2, nt2 = (it + 1) & 3;
                        ldsm4t(vhb[(it + 1) & 1],
                               kbv + ASWZ(ks2 * 16 + trow_l, nt2 * 2 + tseg_l));
                    }
                    const uint32_t* vh4 = vhb[it & 1];
                    mma16816h(o[2 * nt],     pf[ks], vh4);
                    mma16816h(o[2 * nt + 1], pf[ks], vh4 + 2);
                }
            }
        }
    }

    float inv0 = 1.0f / l0, inv1 = 1.0f / l1;
    int r0   = warp * 16 + (lane >> 2);
    int tok0 = qt * 128 + r0;
    int colb = h * HD + (lane & 3) * 2;
    size_t row0a = (size_t)(tok0 * 2 + b) * EMB;
    size_t row1a = (size_t)((tok0 + 8) * 2 + b) * EMB;
    #pragma unroll
    for (int j = 0; j < 8; j++) {
        int col = colb + 8 * j;
        *(uint32_t*)(g_ch + row0a + col) = pack2h(o[j][0] * inv0, o[j][1] * inv0);
        *(uint32_t*)(g_ch + row1a + col) = pack2h(o[j][2] * inv1, o[j][3] * inv1);
    }
}

// ---------------------------------------------------------------------------
// Launch
// ---------------------------------------------------------------------------
extern "C" void kernel_launch(void* const* d_in, const int* in_sizes, int n_in,
                              void* d_out, int out_size)
{
    const float* seq   = (const float*)d_in[0];
    const float* w_qkv = (const float*)d_in[1];
    const float* b_qkv = (const float*)d_in[2];
    const float* w_out = (const float*)d_in[3];
    const float* b_out = (const float*)d_in[4];
    float* out = (float*)d_out;

    __half *sh, *wq, *wo, *ch;
    cudaGetSymbolAddress((void**)&sh, g_sh);
    cudaGetSymbolAddress((void**)&wq, g_wq);
    cudaGetSymbolAddress((void**)&wo, g_wo);
    cudaGetSymbolAddress((void**)&ch, g_ch);

    cudaFuncSetAttribute(gemm_mma_kernel,
                         cudaFuncAttributeMaxDynamicSharedMemorySize, GSMEM);
    cudaFuncSetAttribute(attn_mma_kernel,
                         cudaFuncAttributeMaxDynamicSharedMemorySize, ATTN_SMEM);

    // 0) fused convert: seq + w_qkv + w_out -> fp16 (1 kernel)
    {
        int ntot = N4_SEQ + N4_WQ + N4_WO;
        convert_all_kernel<<<(ntot + 255) / 256, 256>>>(
            (const float4*)seq, (const float4*)w_qkv, (const float4*)w_out);
    }

    // 1) QKV projection -> fp16 Q (scaled), fp16 K, fp16 V (token-major)
    gemm_mma_kernel<<<dim3(F3 / 128, MROWS / 128), 256, GSMEM>>>(
        sh, wq, b_qkv, nullptr, F3, EMB, 1);

    // 2) fused flash attention -> fp16 ctx (V transposed via ldsm.trans)
    attn_mma_kernel<<<dim3(NTOK / 128, BSZ * NH), 256, ATTN_SMEM>>>();

    // 3) output projection -> fp32 out
    gemm_mma_kernel<<<dim3(EMB / 128, MROWS / 128), 256, GSMEM>>>(
        ch, wo, b_out, out, EMB, EMB, 0);
}

// round 15
// speedup vs baseline: 1.0684x; 1.0684x over previous
#include <cuda_runtime.h>
#include <cuda_bf16.h>
#include <cuda_fp16.h>
#include <math_constants.h>
#include <cstdint>

// Problem constants
#define NTOK 2048
#define BSZ  2
#define EMB  1024
#define NH   16
#define HD   64
#define MROWS (NTOK*BSZ)      // 4096
#define F3   (3*EMB)          // 3072
#define QSCALE 0.1803368801111204f   // 0.125 * log2(e)

// -------------------- device scratch (allocation-free) ----------------------
__device__ __half g_sh[(size_t)MROWS * EMB];   // seq fp16 (1-pass)
__device__ __half g_wq[(size_t)F3 * EMB];      // w_qkv fp16 (1-pass)
__device__ __half g_wo[(size_t)EMB * EMB];     // w_out fp16 (1-pass)
__device__ __half g_qf[(size_t)MROWS * EMB];   // Q fp16 (pre-scaled)
__device__ __half g_kf[(size_t)MROWS * EMB];   // K fp16
__device__ __half g_vh0[(size_t)MROWS * EMB];  // V fp16 (token-major)
__device__ __half g_ch[(size_t)MROWS * EMB];   // attn out fp16 (1-pass)

// -------------------- PTX helpers -------------------------------------------
__device__ __forceinline__ uint32_t s2u(const void* p) {
    uint32_t a;
    asm("{ .reg .u64 t; cvta.to.shared.u64 t, %1; cvt.u32.u64 %0, t; }"
        : "=r"(a) : "l"(p));
    return a;
}

__device__ __forceinline__ void cp16(uint32_t dst, const void* src) {
    asm volatile("cp.async.cg.shared.global [%0], [%1], 16;"
                 :: "r"(dst), "l"(src) : "memory");
}
#define CP_COMMIT() asm volatile("cp.async.commit_group;" ::: "memory")

__device__ __forceinline__ void ldsm4(uint32_t* r, uint32_t a) {
    asm volatile("ldmatrix.sync.aligned.m8n8.x4.shared.b16 {%0,%1,%2,%3}, [%4];"
                 : "=r"(r[0]), "=r"(r[1]), "=r"(r[2]), "=r"(r[3]) : "r"(a));
}

// transposing variant (V: token-major smem -> B fragments)
__device__ __forceinline__ void ldsm4t(uint32_t* r, uint32_t a) {
    asm volatile("ldmatrix.sync.aligned.m8n8.x4.trans.shared.b16 {%0,%1,%2,%3}, [%4];"
                 : "=r"(r[0]), "=r"(r[1]), "=r"(r[2]), "=r"(r[3]) : "r"(a));
}

// fp32-accumulate HMMA
__device__ __forceinline__ void mma16816h(float* c, const uint32_t* a,
                                           const uint32_t* b) {
    asm volatile(
        "mma.sync.aligned.m16n8k16.row.col.f32.f16.f16.f32 "
        "{%0,%1,%2,%3}, {%4,%5,%6,%7}, {%8,%9}, {%0,%1,%2,%3};"
        : "+f"(c[0]), "+f"(c[1]), "+f"(c[2]), "+f"(c[3])
        : "r"(a[0]), "r"(a[1]), "r"(a[2]), "r"(a[3]), "r"(b[0]), "r"(b[1]));
}

// fp16-accumulate HMMA (QK logits)
__device__ __forceinline__ void mma16816hh(uint32_t* c, const uint32_t* a,
                                            const uint32_t* b) {
    asm volatile(
        "mma.sync.aligned.m16n8k16.row.col.f16.f16.f16.f16 "
        "{%0,%1}, {%2,%3,%4,%5}, {%6,%7}, {%0,%1};"
        : "+r"(c[0]), "+r"(c[1])
        : "r"(a[0]), "r"(a[1]), "r"(a[2]), "r"(a[3]), "r"(b[0]), "r"(b[1]));
}

__device__ __forceinline__ float ex2(float x) {
    float y;
    asm("ex2.approx.f32 %0, %1;" : "=f"(y) : "f"(x));
    return y;
}

__device__ __forceinline__ uint32_t hmax2u(uint32_t a, uint32_t b) {
    uint32_t d;
    asm("max.f16x2 %0, %1, %2;" : "=r"(d) : "r"(a), "r"(b));
    return d;
}

__device__ __forceinline__ uint32_t hsub2u(uint32_t a, uint32_t b) {
    uint32_t d;
    asm("sub.f16x2 %0, %1, %2;" : "=r"(d) : "r"(a), "r"(b));
    return d;
}

__device__ __forceinline__ uint32_t ex2h2(uint32_t a) {
    uint32_t d;
    asm("ex2.approx.f16x2 %0, %1;" : "=r"(d) : "r"(a));
    return d;
}

__device__ __forceinline__ uint32_t pack2h(float a, float b) {
    __half2 t = __floats2half2_rn(a, b);
    return *reinterpret_cast<uint32_t*>(&t);
}

__device__ __forceinline__ float2 unpack2h(uint32_t u) {
    __half2 t = *reinterpret_cast<__half2*>(&u);
    return __half22float2(t);
}

// -------------------- fused convert: 3 arrays fp32 -> fp16 ------------------
#define N4_SEQ (MROWS * EMB / 4)
#define N4_WQ  (F3 * EMB / 4)
#define N4_WO  (EMB * EMB / 4)

__global__ void convert_all_kernel(const float4* __restrict__ seq,
                                   const float4* __restrict__ wq,
                                   const float4* __restrict__ wo) {
    int i = blockIdx.x * blockDim.x + threadIdx.x;
    const float4* src;
    uint2* dst;
    int k;
    if (i < N4_SEQ) {
        src = seq; dst = (uint2*)g_sh; k = i;
    } else if (i < N4_SEQ + N4_WQ) {
        src = wq; dst = (uint2*)g_wq; k = i - N4_SEQ;
    } else if (i < N4_SEQ + N4_WQ + N4_WO) {
        src = wo; dst = (uint2*)g_wo; k = i - N4_SEQ - N4_WQ;
    } else return;
    float4 x = src[k];
    uint2 o;
    o.x = pack2h(x.x, x.y);
    o.y = pack2h(x.z, x.w);
    dst[k] = o;
}

// -------------------- fp16 1-pass GEMM, K-chunk 32 ---------------------------
// C = A[M][K] * B[N][K]^T + bias[N]; CTA 128x128, 8 warps (32x64 warp tile).
// qkvmode=0: C fp32.  qkvmode=1: N=3072; comp0->g_qf(xQSCALE), comp1->g_kf,
// comp2->g_vh0 (fp16).
#define PITCH  80
#define TILEB  (128 * PITCH)       // 10240
#define STAGEB (2 * TILEB)         // 20480: A, B
#define GSTG   4
#define GSMEM  (GSTG * STAGEB)     // 81920 -> 2 CTAs/SM

#define ARR_A  0
#define ARR_B  TILEB

__global__ void __launch_bounds__(256, 2) gemm_mma_kernel(
    const __half* __restrict__ A, const __half* __restrict__ B,
    const float* __restrict__ bias, float* __restrict__ C,
    int N, int K, int qkvmode)
{
    extern __shared__ char smem[];
    const uint32_t sb = s2u(smem);
    const int tid  = threadIdx.x;
    const int lane = tid & 31;
    const int warp = tid >> 5;
    const int wm   = warp & 3;
    const int wn   = warp >> 2;
    const int row0 = blockIdx.y * 128;
    const int col0 = blockIdx.x * 128;

    float acc[2][8][4];
    #pragma unroll
    for (int i = 0; i < 2; i++)
        #pragma unroll
        for (int j = 0; j < 8; j++)
            #pragma unroll
            for (int v = 0; v < 4; v++) acc[i][j][v] = 0.f;

    const uint32_t a_off = (uint32_t)(lane & 15) * PITCH + (lane >> 4) * 16;
    const uint32_t b_off = (uint32_t)((lane & 7) + ((lane >> 4) & 1) * 8) * PITCH
                         + ((lane >> 3) & 1) * 16;

    const int pr   = tid >> 1;
    const int pseg = (tid & 1) * 2;
    const int nch  = K / 32;

    #define PRODUCE(c)                                                        \
    do {                                                                      \
        uint32_t base = sb + (uint32_t)((c) & 3) * STAGEB;                    \
        size_t gA = (size_t)(row0 + pr) * K + (c) * 32 + pseg * 8;            \
        size_t gB = (size_t)(col0 + pr) * K + (c) * 32 + pseg * 8;            \
        uint32_t so = (uint32_t)pr * PITCH + pseg * 16;                       \
        cp16(base + ARR_A + so,      A + gA);                                 \
        cp16(base + ARR_A + so + 16, A + gA + 8);                             \
        cp16(base + ARR_B + so,      B + gB);                                 \
        cp16(base + ARR_B + so + 16, B + gB + 8);                             \
    } while (0)

    PRODUCE(0); CP_COMMIT();
    PRODUCE(1); CP_COMMIT();
    PRODUCE(2); CP_COMMIT();

    for (int c = 0; c < nch; c++) {
        asm volatile("cp.async.wait_group 2;" ::: "memory");
        __syncthreads();

        if (c + 3 < nch) PRODUCE(c + 3);
        CP_COMMIT();

        const uint32_t st = sb + (uint32_t)(c & 3) * STAGEB;

        #pragma unroll
        for (int ks = 0; ks < 2; ks++) {
            const uint32_t brow = ARR_B + (uint32_t)(wn * 64) * PITCH
                                + ks * 32 + b_off;
            uint32_t ah[2][4], bfr[2][4];
            ldsm4(bfr[0], st + brow);
            #pragma unroll
            for (int mt = 0; mt < 2; mt++) {
                uint32_t ra = (uint32_t)(wm * 32 + mt * 16) * PITCH
                            + ks * 32 + a_off;
                ldsm4(ah[mt], st + ARR_A + ra);
            }
            #pragma unroll
            for (int nt = 0; nt < 4; nt++) {
                if (nt < 3)
                    ldsm4(bfr[(nt + 1) & 1],
                          st + brow + (uint32_t)((nt + 1) * 16) * PITCH);
                const uint32_t* b4 = bfr[nt & 1];
                mma16816h(acc[0][2 * nt],     ah[0], b4);
                mma16816h(acc[1][2 * nt],     ah[1], b4);
                mma16816h(acc[0][2 * nt + 1], ah[0], b4 + 2);
                mma16816h(acc[1][2 * nt + 1], ah[1], b4 + 2);
            }
        }
    }

    const int tr = lane >> 2;
    const int tc = (lane & 3) * 2;
    const int comp = col0 >> 10;
    #pragma unroll
    for (int mt = 0; mt < 2; mt++) {
        #pragma unroll
        for (int n8 = 0; n8 < 8; n8++) {
            int r  = row0 + wm * 32 + mt * 16 + tr;
            int cc = col0 + wn * 64 + n8 * 8 + tc;
            float b0 = bias[cc], b1 = bias[cc + 1];
            float v0 = acc[mt][n8][0] + b0;
            float v1 = acc[mt][n8][1] + b1;
            float v2 = acc[mt][n8][2] + b0;
            float v3 = acc[mt][n8][3] + b1;
            if (qkvmode) {
                int ccl = cc - (comp << 10);
                size_t o0 = (size_t)r * EMB + ccl;
                size_t o1 = (size_t)(r + 8) * EMB + ccl;
                if (comp == 0) {
                    *(uint32_t*)(g_qf + o0) = pack2h(v0 * QSCALE, v1 * QSCALE);
                    *(uint32_t*)(g_qf + o1) = pack2h(v2 * QSCALE, v3 * QSCALE);
                } else if (comp == 1) {
                    *(uint32_t*)(g_kf + o0) = pack2h(v0, v1);
                    *(uint32_t*)(g_kf + o1) = pack2h(v2, v3);
                } else {
                    *(uint32_t*)(g_vh0 + o0) = pack2h(v0, v1);
                    *(uint32_t*)(g_vh0 + o1) = pack2h(v2, v3);
                }
            } else {
                *(float2*)(C + (size_t)r * N + cc)       = make_float2(v0, v1);
                *(float2*)(C + (size_t)(r + 8) * N + cc) = make_float2(v2, v3);
            }
        }
    }
}

// -------------------- flash attention (ldsm.trans V, 64-key stages) ---------
#define AQ    0
#define ABUF  16384
#define ASTG  16384                 // K 8KB + V 8KB
#define A_K   0
#define A_VH  8192
#define ASTAGES 3
#define ATTN_SMEM (ABUF + ASTAGES * ASTG)   // 65536 -> 2 CTAs/SM

#define ASWZ(row, seg) ((uint32_t)(row) * 128 + ((uint32_t)((seg) ^ ((row) & 7)) * 16))

__global__ void __launch_bounds__(256, 2) attn_mma_kernel()
{
    extern __shared__ char smem[];
    const uint32_t sb = s2u(smem);
    const int tid  = threadIdx.x;
    const int lane = tid & 31;
    const int warp = tid >> 5;
    const int qt = blockIdx.x;
    const int bh = blockIdx.y;
    const int b  = bh & 1;
    const int h  = bh >> 1;

    {
        int prow = tid >> 1;
        int psb  = (tid & 1) * 4;
        int qtok = qt * 128 + prow;
        size_t gq = (size_t)(qtok * 2 + b) * EMB + h * HD + psb * 8;
        #pragma unroll
        for (int j = 0; j < 4; j++)
            cp16(sb + AQ + ASWZ(prow, psb + j), g_qf + gq + j * 8);
    }

    const int prow = tid >> 2;
    const int ps2  = (tid & 3) * 2;

    // K and V both token-major in smem (V transposed at ldsm time)
    #define APROD(kt)                                                         \
    do {                                                                      \
        uint32_t bufb = sb + ABUF + (uint32_t)((kt) % ASTAGES) * ASTG;        \
        int tok = (kt) * 64 + prow;                                           \
        size_t g = (size_t)(tok * 2 + b) * EMB + h * HD;                      \
        _Pragma("unroll")                                                     \
        for (int j = 0; j < 2; j++) {                                         \
            int seg = ps2 + j;                                                \
            uint32_t o = ASWZ(prow, seg);                                     \
            cp16(bufb + A_K  + o, g_kf  + g + seg * 8);                       \
            cp16(bufb + A_VH + o, g_vh0 + g + seg * 8);                       \
        }                                                                     \
    } while (0)

    APROD(0); CP_COMMIT();
    APROD(1); CP_COMMIT();

    float o[8][4];
    #pragma unroll
    for (int j = 0; j < 8; j++)
        #pragma unroll
        for (int v = 0; v < 4; v++) o[j][v] = 0.f;
    float m0 = -CUDART_INF_F, m1 = -CUDART_INF_F, l0 = 0.f, l1 = 0.f;
    uint32_t qf[4][4];

    const int brow_l = (lane & 7) + ((lane >> 4) & 1) * 8;  // K (non-trans)
    const int bseg_l = (lane >> 3) & 1;
    const int trow_l = lane & 15;                            // V (trans)
    const int tseg_l = lane >> 4;

    const int NKT = NTOK / 64;
    for (int kt = 0; kt < NKT; kt++) {
        asm volatile("cp.async.wait_group 1;" ::: "memory");
        __syncthreads();

        if (kt + 2 < NKT) APROD(kt + 2);
        CP_COMMIT();

        const uint32_t kb = sb + ABUF + (uint32_t)(kt % ASTAGES) * ASTG;

        if (kt == 0) {
            #pragma unroll
            for (int ks = 0; ks < 4; ks++) {
                int row = warp * 16 + (lane & 15);
                int seg = ks * 2 + (lane >> 4);
                ldsm4(qf[ks], sb + AQ + ASWZ(row, seg));
            }
        }

        // S = Q K^T with fp16 accumulators
        uint32_t sh2[8][2];
        #pragma unroll
        for (int j = 0; j < 8; j++) { sh2[j][0] = 0u; sh2[j][1] = 0u; }

        {
            uint32_t kbf[2][4];
            ldsm4(kbf[0], kb + A_K + ASWZ(brow_l, bseg_l));
            #pragma unroll
            for (int it = 0; it < 16; it++) {
                const int ks = it >> 2, nt = it & 3;
                if (it < 15) {
                    const int ks2 = (it + 1) >> 2, nt2 = (it + 1) & 3;
                    ldsm4(kbf[(it + 1) & 1],
                          kb + A_K + ASWZ(nt2 * 16 + brow_l, ks2 * 2 + bseg_l));
                }
                const uint32_t* k4 = kbf[it & 1];
                mma16816hh(sh2[2 * nt],     qf[ks], k4);
                mma16816hh(sh2[2 * nt + 1], qf[ks], k4 + 2);
            }
        }

        // row maxes (packed f16x2 tree + cross-lane)
        uint32_t mx0 = sh2[0][0], mx1 = sh2[0][1];
        #pragma unroll
        for (int j = 1; j < 8; j++) {
            mx0 = hmax2u(mx0, sh2[j][0]);
            mx1 = hmax2u(mx1, sh2[j][1]);
        }
        mx0 = hmax2u(mx0, __shfl_xor_sync(0xffffffffu, mx0, 1));
        mx0 = hmax2u(mx0, __shfl_xor_sync(0xffffffffu, mx0, 2));
        mx1 = hmax2u(mx1, __shfl_xor_sync(0xffffffffu, mx1, 1));
        mx1 = hmax2u(mx1, __shfl_xor_sync(0xffffffffu, mx1, 2));
        float2 f0 = unpack2h(mx0);
        float2 f1 = unpack2h(mx1);
        float cm0 = fmaxf(f0.x, f0.y);
        float cm1 = fmaxf(f1.x, f1.y);

        float nm0 = fmaxf(m0, cm0), nm1 = fmaxf(m1, cm1);
        float al0 = ex2(m0 - nm0),  al1 = ex2(m1 - nm1);
        m0 = nm0; m1 = nm1;

        uint32_t nm0h, nm1h;
        {
            __half2 t0 = __float2half2_rn(nm0);
            __half2 t1 = __float2half2_rn(nm1);
            nm0h = *reinterpret_cast<uint32_t*>(&t0);
            nm1h = *reinterpret_cast<uint32_t*>(&t1);
        }

        // P fragments in packed half2 (a-fragment layout)
        uint32_t pf[4][4];
        #pragma unroll
        for (int ks = 0; ks < 4; ks++) {
            pf[ks][0] = ex2h2(hsub2u(sh2[2 * ks][0],     nm0h));
            pf[ks][1] = ex2h2(hsub2u(sh2[2 * ks][1],     nm1h));
            pf[ks][2] = ex2h2(hsub2u(sh2[2 * ks + 1][0], nm0h));
            pf[ks][3] = ex2h2(hsub2u(sh2[2 * ks + 1][1], nm1h));
        }

        // row sums: unpack to fp32 (exact; FMA pipe, overlaps MMA)
        float rs0 = 0.f, rs1 = 0.f;
        #pragma unroll
        for (int ks = 0; ks < 4; ks++) {
            float2 a0 = unpack2h(pf[ks][0]);
            float2 a2 = unpack2h(pf[ks][2]);
            rs0 += (a0.x + a0.y) + (a2.x + a2.y);
            float2 a1 = unpack2h(pf[ks][1]);
            float2 a3 = unpack2h(pf[ks][3]);
            rs1 += (a1.x + a1.y) + (a3.x + a3.y);
        }
        rs0 += __shfl_xor_sync(0xffffffffu, rs0, 1);
        rs0 += __shfl_xor_sync(0xffffffffu, rs0, 2);
        rs1 += __shfl_xor_sync(0xffffffffu, rs1, 1);
        rs1 += __shfl_xor_sync(0xffffffffu, rs1, 2);
        l0 = l0 * al0 + rs0;
        l1 = l1 * al1 + rs1;

        #pragma unroll
        for (int j = 0; j < 8; j++) {
            o[j][0] *= al0; o[j][1] *= al0;
            o[j][2] *= al1; o[j][3] *= al1;
        }

        // O += P V  (V loaded token-major, transposed by ldsm.trans)
        {
            uint32_t vhb[2][4];
            ldsm4t(vhb[0], kb + A_VH + ASWZ(trow_l, tseg_l));
            #pragma unroll
            for (int it = 0; it < 16; it++) {
                const int ks = it >> 2, nt = it & 3;
                if (it < 15) {
                    const int ks2 = (it + 1) >> 2, nt2 = (it + 1) & 3;
                    ldsm4t(vhb[(it + 1) & 1],
                           kb + A_VH + ASWZ(ks2 * 16 + trow_l, nt2 * 2 + tseg_l));
                }
                const uint32_t* vh4 = vhb[it & 1];
                mma16816h(o[2 * nt],     pf[ks], vh4);
                mma16816h(o[2 * nt + 1], pf[ks], vh4 + 2);
            }
        }
    }

    float inv0 = 1.0f / l0, inv1 = 1.0f / l1;
    int r0   = warp * 16 + (lane >> 2);
    int tok0 = qt * 128 + r0;
    int colb = h * HD + (lane & 3) * 2;
    size_t row0a = (size_t)(tok0 * 2 + b) * EMB;
    size_t row1a = (size_t)((tok0 + 8) * 2 + b) * EMB;
    #pragma unroll
    for (int j = 0; j < 8; j++) {
        int col = colb + 8 * j;
        *(uint32_t*)(g_ch + row0a + col) = pack2h(o[j][0] * inv0, o[j][1] * inv0);
        *(uint32_t*)(g_ch + row1a + col) = pack2h(o[j][2] * inv1, o[j][3] * inv1);
    }
}

// ---------------------------------------------------------------------------
// Launch
// ---------------------------------------------------------------------------
extern "C" void kernel_launch(void* const* d_in, const int* in_sizes, int n_in,
                              void* d_out, int out_size)
{
    const float* seq   = (const float*)d_in[0];
    const float* w_qkv = (const float*)d_in[1];
    const float* b_qkv = (const float*)d_in[2];
    const float* w_out = (const float*)d_in[3];
    const float* b_out = (const float*)d_in[4];
    float* out = (float*)d_out;

    __half *sh, *wq, *wo, *ch;
    cudaGetSymbolAddress((void**)&sh, g_sh);
    cudaGetSymbolAddress((void**)&wq, g_wq);
    cudaGetSymbolAddress((void**)&wo, g_wo);
    cudaGetSymbolAddress((void**)&ch, g_ch);

    cudaFuncSetAttribute(gemm_mma_kernel,
                         cudaFuncAttributeMaxDynamicSharedMemorySize, GSMEM);
    cudaFuncSetAttribute(attn_mma_kernel,
                         cudaFuncAttributeMaxDynamicSharedMemorySize, ATTN_SMEM);

    // 0) fused convert: seq + w_qkv + w_out -> fp16 (1 kernel)
    {
        int ntot = N4_SEQ + N4_WQ + N4_WO;
        convert_all_kernel<<<(ntot + 255) / 256, 256>>>(
            (const float4*)seq, (const float4*)w_qkv, (const float4*)w_out);
    }

    // 1) QKV projection -> fp16 Q (scaled), fp16 K, fp16 V (token-major)
    gemm_mma_kernel<<<dim3(F3 / 128, MROWS / 128), 256, GSMEM>>>(
        sh, wq, b_qkv, nullptr, F3, EMB, 1);

    // 2) fused flash attention -> fp16 ctx (V transposed via ldsm.trans)
    attn_mma_kernel<<<dim3(NTOK / 128, BSZ * NH), 256, ATTN_SMEM>>>();

    // 3) output projection -> fp32 out
    gemm_mma_kernel<<<dim3(EMB / 128, MROWS / 128), 256, GSMEM>>>(
        ch, wo, b_out, out, EMB, EMB, 0);
}

// round 16
// speedup vs baseline: 1.0765x; 1.0076x over previous
#include <cuda_runtime.h>
#include <cuda_bf16.h>
#include <cuda_fp16.h>
#include <math_constants.h>
#include <cstdint>

// Problem constants
#define NTOK 2048
#define BSZ  2
#define EMB  1024
#define NH   16
#define HD   64
#define MROWS (NTOK*BSZ)      // 4096
#define F3   (3*EMB)          // 3072
#define QSCALE 0.1803368801111204f   // 0.125 * log2(e)

// -------------------- device scratch (allocation-free) ----------------------
__device__ __half g_sh[(size_t)MROWS * EMB];   // seq fp16 (1-pass)
__device__ __half g_wq[(size_t)F3 * EMB];      // w_qkv fp16 (1-pass)
__device__ __half g_wo[(size_t)EMB * EMB];     // w_out fp16 (1-pass)
__device__ __half g_qf[(size_t)MROWS * EMB];   // Q fp16 (pre-scaled)
__device__ __half g_kf[(size_t)MROWS * EMB];   // K fp16
__device__ __half g_vh0[(size_t)MROWS * EMB];  // V fp16 (token-major)
__device__ __half g_ch[(size_t)MROWS * EMB];   // attn out fp16 (1-pass)

// -------------------- PTX helpers -------------------------------------------
__device__ __forceinline__ uint32_t s2u(const void* p) {
    uint32_t a;
    asm("{ .reg .u64 t; cvta.to.shared.u64 t, %1; cvt.u32.u64 %0, t; }"
        : "=r"(a) : "l"(p));
    return a;
}

__device__ __forceinline__ void cp16(uint32_t dst, const void* src) {
    asm volatile("cp.async.cg.shared.global [%0], [%1], 16;"
                 :: "r"(dst), "l"(src) : "memory");
}
#define CP_COMMIT() asm volatile("cp.async.commit_group;" ::: "memory")

__device__ __forceinline__ void ldsm4(uint32_t* r, uint32_t a) {
    asm volatile("ldmatrix.sync.aligned.m8n8.x4.shared.b16 {%0,%1,%2,%3}, [%4];"
                 : "=r"(r[0]), "=r"(r[1]), "=r"(r[2]), "=r"(r[3]) : "r"(a));
}

// transposing variant (V: token-major smem -> B fragments)
__device__ __forceinline__ void ldsm4t(uint32_t* r, uint32_t a) {
    asm volatile("ldmatrix.sync.aligned.m8n8.x4.trans.shared.b16 {%0,%1,%2,%3}, [%4];"
                 : "=r"(r[0]), "=r"(r[1]), "=r"(r[2]), "=r"(r[3]) : "r"(a));
}

// fp32-accumulate HMMA
__device__ __forceinline__ void mma16816h(float* c, const uint32_t* a,
                                           const uint32_t* b) {
    asm volatile(
        "mma.sync.aligned.m16n8k16.row.col.f32.f16.f16.f32 "
        "{%0,%1,%2,%3}, {%4,%5,%6,%7}, {%8,%9}, {%0,%1,%2,%3};"
        : "+f"(c[0]), "+f"(c[1]), "+f"(c[2]), "+f"(c[3])
        : "r"(a[0]), "r"(a[1]), "r"(a[2]), "r"(a[3]), "r"(b[0]), "r"(b[1]));
}

// fp16-accumulate HMMA (QK logits)
__device__ __forceinline__ void mma16816hh(uint32_t* c, const uint32_t* a,
                                            const uint32_t* b) {
    asm volatile(
        "mma.sync.aligned.m16n8k16.row.col.f16.f16.f16.f16 "
        "{%0,%1}, {%2,%3,%4,%5}, {%6,%7}, {%0,%1};"
        : "+r"(c[0]), "+r"(c[1])
        : "r"(a[0]), "r"(a[1]), "r"(a[2]), "r"(a[3]), "r"(b[0]), "r"(b[1]));
}

__device__ __forceinline__ float ex2(float x) {
    float y;
    asm("ex2.approx.f32 %0, %1;" : "=f"(y) : "f"(x));
    return y;
}

__device__ __forceinline__ uint32_t hmax2u(uint32_t a, uint32_t b) {
    uint32_t d;
    asm("max.f16x2 %0, %1, %2;" : "=r"(d) : "r"(a), "r"(b));
    return d;
}

__device__ __forceinline__ uint32_t hsub2u(uint32_t a, uint32_t b) {
    uint32_t d;
    asm("sub.f16x2 %0, %1, %2;" : "=r"(d) : "r"(a), "r"(b));
    return d;
}

__device__ __forceinline__ uint32_t ex2h2(uint32_t a) {
    uint32_t d;
    asm("ex2.approx.f16x2 %0, %1;" : "=r"(d) : "r"(a));
    return d;
}

__device__ __forceinline__ uint32_t pack2h(float a, float b) {
    __half2 t = __floats2half2_rn(a, b);
    return *reinterpret_cast<uint32_t*>(&t);
}

__device__ __forceinline__ float2 unpack2h(uint32_t u) {
    __half2 t = *reinterpret_cast<__half2*>(&u);
    return __half22float2(t);
}

// -------------------- fused convert: 3 arrays fp32 -> fp16 -------------------
// 4 float4 loads per thread (front-batched for MLP), 2 uint4 stores.
#define N16_SEQ (MROWS * EMB / 16)
#define N16_WQ  (F3 * EMB / 16)
#define N16_WO  (EMB * EMB / 16)

__global__ void convert_all_kernel(const float4* __restrict__ seq,
                                   const float4* __restrict__ wq,
                                   const float4* __restrict__ wo) {
    int i = blockIdx.x * blockDim.x + threadIdx.x;   // 16-float granule index
    const float4* src;
    uint2* dst;
    int k;
    if (i < N16_SEQ) {
        src = seq; dst = (uint2*)g_sh; k = i;
    } else if (i < N16_SEQ + N16_WQ) {
        src = wq; dst = (uint2*)g_wq; k = i - N16_SEQ;
    } else if (i < N16_SEQ + N16_WQ + N16_WO) {
        src = wo; dst = (uint2*)g_wo; k = i - N16_SEQ - N16_WQ;
    } else return;

    float4 x0 = src[4 * k + 0];
    float4 x1 = src[4 * k + 1];
    float4 x2 = src[4 * k + 2];
    float4 x3 = src[4 * k + 3];
    uint4 o0, o1;
    o0.x = pack2h(x0.x, x0.y); o0.y = pack2h(x0.z, x0.w);
    o0.z = pack2h(x1.x, x1.y); o0.w = pack2h(x1.z, x1.w);
    o1.x = pack2h(x2.x, x2.y); o1.y = pack2h(x2.z, x2.w);
    o1.z = pack2h(x3.x, x3.y); o1.w = pack2h(x3.z, x3.w);
    *(uint4*)(dst + 4 * k)     = o0;
    *(uint4*)(dst + 4 * k + 2) = o1;
}

// -------------------- fp16 1-pass GEMM, K-chunk 32 ---------------------------
// C = A[M][K] * B[N][K]^T + bias[N]; CTA 128x128, 8 warps (32x64 warp tile).
// qkvmode=0: C fp32.  qkvmode=1: N=3072; comp0->g_qf(xQSCALE), comp1->g_kf,
// comp2->g_vh0 (fp16).
#define PITCH  80
#define TILEB  (128 * PITCH)       // 10240
#define STAGEB (2 * TILEB)         // 20480: A, B
#define GSTG   4
#define GSMEM  (GSTG * STAGEB)     // 81920 -> 2 CTAs/SM

#define ARR_A  0
#define ARR_B  TILEB

__global__ void __launch_bounds__(256, 2) gemm_mma_kernel(
    const __half* __restrict__ A, const __half* __restrict__ B,
    const float* __restrict__ bias, float* __restrict__ C,
    int N, int K, int qkvmode)
{
    extern __shared__ char smem[];
    const uint32_t sb = s2u(smem);
    const int tid  = threadIdx.x;
    const int lane = tid & 31;
    const int warp = tid >> 5;
    const int wm   = warp & 3;
    const int wn   = warp >> 2;
    const int row0 = blockIdx.y * 128;
    const int col0 = blockIdx.x * 128;

    float acc[2][8][4];
    #pragma unroll
    for (int i = 0; i < 2; i++)
        #pragma unroll
        for (int j = 0; j < 8; j++)
            #pragma unroll
            for (int v = 0; v < 4; v++) acc[i][j][v] = 0.f;

    const uint32_t a_off = (uint32_t)(lane & 15) * PITCH + (lane >> 4) * 16;
    const uint32_t b_off = (uint32_t)((lane & 7) + ((lane >> 4) & 1) * 8) * PITCH
                         + ((lane >> 3) & 1) * 16;

    const int pr   = tid >> 1;
    const int pseg = (tid & 1) * 2;
    const int nch  = K / 32;

    #define PRODUCE(c)                                                        \
    do {                                                                      \
        uint32_t base = sb + (uint32_t)((c) & 3) * STAGEB;                    \
        size_t gA = (size_t)(row0 + pr) * K + (c) * 32 + pseg * 8;            \
        size_t gB = (size_t)(col0 + pr) * K + (c) * 32 + pseg * 8;            \
        uint32_t so = (uint32_t)pr * PITCH + pseg * 16;                       \
        cp16(base + ARR_A + so,      A + gA);                                 \
        cp16(base + ARR_A + so + 16, A + gA + 8);                             \
        cp16(base + ARR_B + so,      B + gB);                                 \
        cp16(base + ARR_B + so + 16, B + gB + 8);                             \
    } while (0)

    PRODUCE(0); CP_COMMIT();
    PRODUCE(1); CP_COMMIT();
    PRODUCE(2); CP_COMMIT();

    for (int c = 0; c < nch; c++) {
        asm volatile("cp.async.wait_group 2;" ::: "memory");
        __syncthreads();

        if (c + 3 < nch) PRODUCE(c + 3);
        CP_COMMIT();

        const uint32_t st = sb + (uint32_t)(c & 3) * STAGEB;

        #pragma unroll
        for (int ks = 0; ks < 2; ks++) {
            const uint32_t brow = ARR_B + (uint32_t)(wn * 64) * PITCH
                                + ks * 32 + b_off;
            uint32_t ah[2][4], bfr[2][4];
            ldsm4(bfr[0], st + brow);
            #pragma unroll
            for (int mt = 0; mt < 2; mt++) {
                uint32_t ra = (uint32_t)(wm * 32 + mt * 16) * PITCH
                            + ks * 32 + a_off;
                ldsm4(ah[mt], st + ARR_A + ra);
            }
            #pragma unroll
            for (int nt = 0; nt < 4; nt++) {
                if (nt < 3)
                    ldsm4(bfr[(nt + 1) & 1],
                          st + brow + (uint32_t)((nt + 1) * 16) * PITCH);
                const uint32_t* b4 = bfr[nt & 1];
                mma16816h(acc[0][2 * nt],     ah[0], b4);
                mma16816h(acc[1][2 * nt],     ah[1], b4);
                mma16816h(acc[0][2 * nt + 1], ah[0], b4 + 2);
                mma16816h(acc[1][2 * nt + 1], ah[1], b4 + 2);
            }
        }
    }

    const int tr = lane >> 2;
    const int tc = (lane & 3) * 2;
    const int comp = col0 >> 10;
    #pragma unroll
    for (int mt = 0; mt < 2; mt++) {
        #pragma unroll
        for (int n4i = 0; n4i < 4; n4i++) {
            // pair adjacent n8 tiles -> 4 contiguous floats per row fragment? No:
            // fragments are 2 cols each, tiles 8 cols apart; keep per-tile stores
            #pragma unroll
            for (int half = 0; half < 2; half++) {
                int n8 = n4i * 2 + half;
                int r  = row0 + wm * 32 + mt * 16 + tr;
                int cc = col0 + wn * 64 + n8 * 8 + tc;
                float b0 = bias[cc], b1 = bias[cc + 1];
                float v0 = acc[mt][n8][0] + b0;
                float v1 = acc[mt][n8][1] + b1;
                float v2 = acc[mt][n8][2] + b0;
                float v3 = acc[mt][n8][3] + b1;
                if (qkvmode) {
                    int ccl = cc - (comp << 10);
                    size_t o0 = (size_t)r * EMB + ccl;
                    size_t o1 = (size_t)(r + 8) * EMB + ccl;
                    if (comp == 0) {
                        *(uint32_t*)(g_qf + o0) = pack2h(v0 * QSCALE, v1 * QSCALE);
                        *(uint32_t*)(g_qf + o1) = pack2h(v2 * QSCALE, v3 * QSCALE);
                    } else if (comp == 1) {
                        *(uint32_t*)(g_kf + o0) = pack2h(v0, v1);
                        *(uint32_t*)(g_kf + o1) = pack2h(v2, v3);
                    } else {
                        *(uint32_t*)(g_vh0 + o0) = pack2h(v0, v1);
                        *(uint32_t*)(g_vh0 + o1) = pack2h(v2, v3);
                    }
                } else {
                    *(float2*)(C + (size_t)r * N + cc)       = make_float2(v0, v1);
                    *(float2*)(C + (size_t)(r + 8) * N + cc) = make_float2(v2, v3);
                }
            }
        }
    }
}

// -------------------- flash attention (ldsm.trans V, 64-key stages) ---------
#define AQ    0
#define ABUF  16384
#define ASTG  16384                 // K 8KB + V 8KB
#define A_K   0
#define A_VH  8192
#define ASTAGES 3
#define ATTN_SMEM (ABUF + ASTAGES * ASTG)   // 65536 -> 2 CTAs/SM

#define ASWZ(row, seg) ((uint32_t)(row) * 128 + ((uint32_t)((seg) ^ ((row) & 7)) * 16))

__global__ void __launch_bounds__(256, 2) attn_mma_kernel()
{
    extern __shared__ char smem[];
    const uint32_t sb = s2u(smem);
    const int tid  = threadIdx.x;
    const int lane = tid & 31;
    const int warp = tid >> 5;
    const int qt = blockIdx.x;
    const int bh = blockIdx.y;
    const int b  = bh & 1;
    const int h  = bh >> 1;

    {
        int prow = tid >> 1;
        int psb  = (tid & 1) * 4;
        int qtok = qt * 128 + prow;
        size_t gq = (size_t)(qtok * 2 + b) * EMB + h * HD + psb * 8;
        #pragma unroll
        for (int j = 0; j < 4; j++)
            cp16(sb + AQ + ASWZ(prow, psb + j), g_qf + gq + j * 8);
    }

    const int prow = tid >> 2;
    const int ps2  = (tid & 3) * 2;

    // K and V both token-major in smem (V transposed at ldsm time)
    #define APROD(kt)                                                         \
    do {                                                                      \
        uint32_t bufb = sb + ABUF + (uint32_t)((kt) % ASTAGES) * ASTG;        \
        int tok = (kt) * 64 + prow;                                           \
        size_t g = (size_t)(tok * 2 + b) * EMB + h * HD;                      \
        _Pragma("unroll")                                                     \
        for (int j = 0; j < 2; j++) {                                         \
            int seg = ps2 + j;                                                \
            uint32_t o = ASWZ(prow, seg);                                     \
            cp16(bufb + A_K  + o, g_kf  + g + seg * 8);                       \
            cp16(bufb + A_VH + o, g_vh0 + g + seg * 8);                       \
        }                                                                     \
    } while (0)

    APROD(0); CP_COMMIT();
    APROD(1); CP_COMMIT();

    float o[8][4];
    #pragma unroll
    for (int j = 0; j < 8; j++)
        #pragma unroll
        for (int v = 0; v < 4; v++) o[j][v] = 0.f;
    float m0 = -CUDART_INF_F, m1 = -CUDART_INF_F, l0 = 0.f, l1 = 0.f;
    uint32_t qf[4][4];

    const int brow_l = (lane & 7) + ((lane >> 4) & 1) * 8;  // K (non-trans)
    const int bseg_l = (lane >> 3) & 1;
    const int trow_l = lane & 15;                            // V (trans)
    const int tseg_l = lane >> 4;

    // hoisted Q-load: wait for stage 0 (leaves stage 1 pending), load Q frags
    asm volatile("cp.async.wait_group 1;" ::: "memory");
    __syncthreads();
    #pragma unroll
    for (int ks = 0; ks < 4; ks++) {
        int row = warp * 16 + (lane & 15);
        int seg = ks * 2 + (lane >> 4);
        ldsm4(qf[ks], sb + AQ + ASWZ(row, seg));
    }

    const int NKT = NTOK / 64;
    for (int kt = 0; kt < NKT; kt++) {
        if (kt > 0) {
            asm volatile("cp.async.wait_group 1;" ::: "memory");
            __syncthreads();
        }

        if (kt + 2 < NKT) APROD(kt + 2);
        CP_COMMIT();

        const uint32_t kb = sb + ABUF + (uint32_t)(kt % ASTAGES) * ASTG;

        // S = Q K^T with fp16 accumulators
        uint32_t sh2[8][2];
        #pragma unroll
        for (int j = 0; j < 8; j++) { sh2[j][0] = 0u; sh2[j][1] = 0u; }

        {
            uint32_t kbf[2][4];
            ldsm4(kbf[0], kb + A_K + ASWZ(brow_l, bseg_l));
            #pragma unroll
            for (int it = 0; it < 16; it++) {
                const int ks = it >> 2, nt = it & 3;
                if (it < 15) {
                    const int ks2 = (it + 1) >> 2, nt2 = (it + 1) & 3;
                    ldsm4(kbf[(it + 1) & 1],
                          kb + A_K + ASWZ(nt2 * 16 + brow_l, ks2 * 2 + bseg_l));
                }
                const uint32_t* k4 = kbf[it & 1];
                mma16816hh(sh2[2 * nt],     qf[ks], k4);
                mma16816hh(sh2[2 * nt + 1], qf[ks], k4 + 2);
            }
        }

        // row maxes (packed f16x2 tree + cross-lane)
        uint32_t mx0 = sh2[0][0], mx1 = sh2[0][1];
        #pragma unroll
        for (int j = 1; j < 8; j++) {
            mx0 = hmax2u(mx0, sh2[j][0]);
            mx1 = hmax2u(mx1, sh2[j][1]);
        }
        mx0 = hmax2u(mx0, __shfl_xor_sync(0xffffffffu, mx0, 1));
        mx0 = hmax2u(mx0, __shfl_xor_sync(0xffffffffu, mx0, 2));
        mx1 = hmax2u(mx1, __shfl_xor_sync(0xffffffffu, mx1, 1));
        mx1 = hmax2u(mx1, __shfl_xor_sync(0xffffffffu, mx1, 2));
        float2 f0 = unpack2h(mx0);
        float2 f1 = unpack2h(mx1);
        float cm0 = fmaxf(f0.x, f0.y);
        float cm1 = fmaxf(f1.x, f1.y);

        float nm0 = fmaxf(m0, cm0), nm1 = fmaxf(m1, cm1);
        float al0 = ex2(m0 - nm0),  al1 = ex2(m1 - nm1);
        m0 = nm0; m1 = nm1;

        uint32_t nm0h, nm1h;
        {
            __half2 t0 = __float2half2_rn(nm0);
            __half2 t1 = __float2half2_rn(nm1);
            nm0h = *reinterpret_cast<uint32_t*>(&t0);
            nm1h = *reinterpret_cast<uint32_t*>(&t1);
        }

        // P fragments in packed half2 (a-fragment layout)
        uint32_t pf[4][4];
        #pragma unroll
        for (int ks = 0; ks < 4; ks++) {
            pf[ks][0] = ex2h2(hsub2u(sh2[2 * ks][0],     nm0h));
            pf[ks][1] = ex2h2(hsub2u(sh2[2 * ks][1],     nm1h));
            pf[ks][2] = ex2h2(hsub2u(sh2[2 * ks + 1][0], nm0h));
            pf[ks][3] = ex2h2(hsub2u(sh2[2 * ks + 1][1], nm1h));
        }

        // row sums: unpack to fp32 (exact; FMA pipe, overlaps MMA)
        float rs0 = 0.f, rs1 = 0.f;
        #pragma unroll
        for (int ks = 0; ks < 4; ks++) {
            float2 a0 = unpack2h(pf[ks][0]);
            float2 a2 = unpack2h(pf[ks][2]);
            rs0 += (a0.x + a0.y) + (a2.x + a2.y);
            float2 a1 = unpack2h(pf[ks][1]);
            float2 a3 = unpack2h(pf[ks][3]);
            rs1 += (a1.x + a1.y) + (a3.x + a3.y);
        }
        rs0 += __shfl_xor_sync(0xffffffffu, rs0, 1);
        rs0 += __shfl_xor_sync(0xffffffffu, rs0, 2);
        rs1 += __shfl_xor_sync(0xffffffffu, rs1, 1);
        rs1 += __shfl_xor_sync(0xffffffffu, rs1, 2);
        l0 = l0 * al0 + rs0;
        l1 = l1 * al1 + rs1;

        #pragma unroll
        for (int j = 0; j < 8; j++) {
            o[j][0] *= al0; o[j][1] *= al0;
            o[j][2] *= al1; o[j][3] *= al1;
        }

        // O += P V  (V loaded token-major, transposed by ldsm.trans)
        {
            uint32_t vhb[2][4];
            ldsm4t(vhb[0], kb + A_VH + ASWZ(trow_l, tseg_l));
            #pragma unroll
            for (int it = 0; it < 16; it++) {
                const int ks = it >> 2, nt = it & 3;
                if (it < 15) {
                    const int ks2 = (it + 1) >> 2, nt2 = (it + 1) & 3;
                    ldsm4t(vhb[(it + 1) & 1],
                           kb + A_VH + ASWZ(ks2 * 16 + trow_l, nt2 * 2 + tseg_l));
                }
                const uint32_t* vh4 = vhb[it & 1];
                mma16816h(o[2 * nt],     pf[ks], vh4);
                mma16816h(o[2 * nt + 1], pf[ks], vh4 + 2);
            }
        }
    }

    float inv0 = 1.0f / l0, inv1 = 1.0f / l1;
    int r0   = warp * 16 + (lane >> 2);
    int tok0 = qt * 128 + r0;
    int colb = h * HD + (lane & 3) * 2;
    size_t row0a = (size_t)(tok0 * 2 + b) * EMB;
    size_t row1a = (size_t)((tok0 + 8) * 2 + b) * EMB;
    #pragma unroll
    for (int j = 0; j < 8; j++) {
        int col = colb + 8 * j;
        *(uint32_t*)(g_ch + row0a + col) = pack2h(o[j][0] * inv0, o[j][1] * inv0);
        *(uint32_t*)(g_ch + row1a + col) = pack2h(o[j][2] * inv1, o[j][3] * inv1);
    }
}

// ---------------------------------------------------------------------------
// Launch
// ---------------------------------------------------------------------------
extern "C" void kernel_launch(void* const* d_in, const int* in_sizes, int n_in,
                              void* d_out, int out_size)
{
    const float* seq   = (const float*)d_in[0];
    const float* w_qkv = (const float*)d_in[1];
    const float* b_qkv = (const float*)d_in[2];
    const float* w_out = (const float*)d_in[3];
    const float* b_out = (const float*)d_in[4];
    float* out = (float*)d_out;

    __half *sh, *wq, *wo, *ch;
    cudaGetSymbolAddress((void**)&sh, g_sh);
    cudaGetSymbolAddress((void**)&wq, g_wq);
    cudaGetSymbolAddress((void**)&wo, g_wo);
    cudaGetSymbolAddress((void**)&ch, g_ch);

    cudaFuncSetAttribute(gemm_mma_kernel,
                         cudaFuncAttributeMaxDynamicSharedMemorySize, GSMEM);
    cudaFuncSetAttribute(attn_mma_kernel,
                         cudaFuncAttributeMaxDynamicSharedMemorySize, ATTN_SMEM);

    // 0) fused convert: seq + w_qkv + w_out -> fp16 (1 kernel, 16 floats/thread)
    {
        int ntot = N16_SEQ + N16_WQ + N16_WO;
        convert_all_kernel<<<(ntot + 255) / 256, 256>>>(
            (const float4*)seq, (const float4*)w_qkv, (const float4*)w_out);
    }

    // 1) QKV projection -> fp16 Q (scaled), fp16 K, fp16 V (token-major)
    gemm_mma_kernel<<<dim3(F3 / 128, MROWS / 128), 256, GSMEM>>>(
        sh, wq, b_qkv, nullptr, F3, EMB, 1);

    // 2) fused flash attention -> fp16 ctx (V transposed via ldsm.trans)
    attn_mma_kernel<<<dim3(NTOK / 128, BSZ * NH), 256, ATTN_SMEM>>>();

    // 3) output projection -> fp32 out
    gemm_mma_kernel<<<dim3(EMB / 128, MROWS / 128), 256, GSMEM>>>(
        ch, wo, b_out, out, EMB, EMB, 0);
}